// round 12
// baseline (speedup 1.0000x reference)
#include <cuda_runtime.h>
#include <cuda_bf16.h>
#include <cstdint>

#define B_    16
#define TRG_  512
#define SRC_  1024
#define ENC_  1024
#define TRGD_ 1024

// -------- packed bf16 hi/lo scratch: uint2 = (hi bf16x2, lo bf16x2) per k-pair
__device__ uint2 g_Hd[(long)B_ * TRG_ * TRGD_ / 2];  // hidden   [t][d2]
__device__ uint2 g_Eo[(long)B_ * SRC_ * ENC_ / 2];   // enc_out  [s][e2]
__device__ uint2 g_Wt[(long)ENC_ * TRGD_ / 2];       // W^T      [e][d2]
__device__ uint2 g_Hp[(long)B_ * TRG_ * ENC_ / 2];   // hidden@W [t][e2]
__device__ uint2 g_Wg[(long)B_ * TRG_ * SRC_ / 2];   // weights  [t][s2]
__device__ uint2 g_Ev[(long)B_ * SRC_ / 2 * TRGD_];  // enc_val  [s2][d] (NN pairs)

// ---------------- helpers ----------------
__device__ __forceinline__ uint32_t s2u(const void* p) {
    uint32_t a;
    asm("{ .reg .u64 t; cvta.to.shared.u64 t, %1; cvt.u32.u64 %0, t; }"
        : "=r"(a) : "l"(p));
    return a;
}
// split (v0, v1) -> packed bf16x2 hi (v0 low half) + packed bf16x2 lo residual
__device__ __forceinline__ uint2 bf16split2(float v0, float v1) {
    __nv_bfloat162 h = __floats2bfloat162_rn(v0, v1);
    uint32_t ph = *reinterpret_cast<uint32_t*>(&h);
    float h0 = __uint_as_float(ph << 16);
    float h1 = __uint_as_float(ph & 0xFFFF0000u);
    __nv_bfloat162 l = __floats2bfloat162_rn(v0 - h0, v1 - h1);
    uint2 r;
    r.x = ph;
    r.y = *reinterpret_cast<uint32_t*>(&l);
    return r;
}
__device__ __forceinline__ void cp16(uint32_t d, const void* s) {
    asm volatile("cp.async.cg.shared.global [%0], [%1], 16;" :: "r"(d), "l"(s));
}
#define CP_COMMIT() asm volatile("cp.async.commit_group;" ::: "memory")

#define MMA_BF16(acc, a0, a1, a2, a3, b0, b1) \
    asm volatile( \
        "mma.sync.aligned.m16n8k16.row.col.f32.bf16.bf16.f32 " \
        "{%0,%1,%2,%3}, {%4,%5,%6,%7}, {%8,%9}, {%0,%1,%2,%3};" \
        : "+f"((acc)[0]), "+f"((acc)[1]), "+f"((acc)[2]), "+f"((acc)[3]) \
        : "r"(a0), "r"(a1), "r"(a2), "r"(a3), "r"(b0), "r"(b1))

// ---------------------------------------------------------------------------
// bf16x3 GEMM: D[m,n] = sum_k A[m,k]*B[n,k]; inputs pre-split, hi/lo packed
// TOGETHER per k-pair (uint2) -> every fragment is ONE LDS.64.
// BM=BN=128, BK=32, 2-stage cp.async, 256 thr, warp tile 32x64.
//   BNN=false: B K-major [n][k2] -> smem [n][20] uint2   (20 % 16 == 4: CF)
//   BNN=true : B NN pairs [k2][n] -> smem [k2][132] uint2 (132 % 16 == 4: CF)
// EPI: 0 = fp32 out, 1 = masked fp32 out, 2 = packed uint2 out.
// ---------------------------------------------------------------------------
template<int EPI, bool BNN>
__global__ __launch_bounds__(256, 2)
void gemm_bf16x3(const uint2* __restrict__ Ag, const uint2* __restrict__ Bg,
                 float* __restrict__ Cg, uint2* __restrict__ C2,
                 const float* __restrict__ maskg,
                 int M, int N, int K, long sA, long sB, long sC)
{
    constexpr int STAGE = 5120;             // uint2 per stage (40KB)
    constexpr int OA = 0, OB = 2560;

    extern __shared__ uint2 smu[];

    const int tid  = threadIdx.x;
    const int wid  = tid >> 5, lane = tid & 31;
    const int wy   = wid >> 1, wx = wid & 1;
    const int bz   = blockIdx.z;
    const int bm   = blockIdx.y * 128, bn = blockIdx.x * 128;
    const int K2   = K >> 1;

    const uint2* Aptr = Ag + (long)bz * sA + (long)bm * K2;
    const uint2* Bptr = BNN ? (Bg + (long)bz * sB)
                            : (Bg + (long)bz * sB + (long)bn * K2);

    auto load_stage = [&](int s, int kc) {
        uint2* st = smu + s * STAGE;
        const int k2b = kc * 16;
#pragma unroll
        for (int i = 0; i < 4; i++) {
            int id = tid + 256 * i;
            int row = id >> 3, ch = (id & 7) * 2;
            cp16(s2u(st + OA + row * 20 + ch), Aptr + (long)row * K2 + k2b + ch);
        }
        if (BNN) {
#pragma unroll
            for (int i = 0; i < 4; i++) {
                int id = tid + 256 * i;
                int r = id >> 6, c2 = (id & 63) * 2;
                cp16(s2u(st + OB + r * 132 + c2),
                     Bptr + (long)(k2b + r) * N + bn + c2);
            }
        } else {
#pragma unroll
            for (int i = 0; i < 4; i++) {
                int id = tid + 256 * i;
                int row = id >> 3, ch = (id & 7) * 2;
                cp16(s2u(st + OB + row * 20 + ch), Bptr + (long)row * K2 + k2b + ch);
            }
        }
    };

    float acc[2][8][4];
#pragma unroll
    for (int i = 0; i < 2; i++)
#pragma unroll
        for (int j = 0; j < 8; j++)
#pragma unroll
            for (int v = 0; v < 4; v++) acc[i][j][v] = 0.0f;

    const int nch = K / 32;
    load_stage(0, 0); CP_COMMIT();

    const int aBase = (wy * 32 + (lane >> 2)) * 20 + (lane & 3);
    const int bBase = BNN ? ((lane & 3) * 132 + wx * 64 + (lane >> 2))
                          : ((wx * 64 + (lane >> 2)) * 20 + (lane & 3));

    for (int kc = 0; kc < nch; kc++) {
        if (kc + 1 < nch) {
            load_stage((kc + 1) & 1, kc + 1);
            CP_COMMIT();
            asm volatile("cp.async.wait_group 1;" ::: "memory");
        } else {
            asm volatile("cp.async.wait_group 0;" ::: "memory");
        }
        __syncthreads();

        const uint2* st = smu + (kc & 1) * STAGE;
        const uint2* sA = st + OA;
        const uint2* sB = st + OB;

#pragma unroll
        for (int ks = 0; ks < 2; ks++) {
            uint32_t ah[2][4], al[2][4];
#pragma unroll
            for (int i = 0; i < 2; i++) {
                const uint2* p = sA + aBase + ks * 8 + i * 320;
                uint2 v0 = p[0], v1 = p[160], v2 = p[4], v3 = p[164];
                ah[i][0] = v0.x; al[i][0] = v0.y;
                ah[i][1] = v1.x; al[i][1] = v1.y;
                ah[i][2] = v2.x; al[i][2] = v2.y;
                ah[i][3] = v3.x; al[i][3] = v3.y;
            }
            const int bk = bBase + (BNN ? ks * 8 * 132 : ks * 8);
            auto loadB = [&](int j, uint2* b) {
                if (BNN) {
                    const uint2* p = sB + bk + j * 8;
                    b[0] = p[0]; b[1] = p[528];      // +4*132
                } else {
                    const uint2* p = sB + bk + j * 160;
                    b[0] = p[0]; b[1] = p[4];
                }
            };
            uint2 b0[2], b1[2];
            loadB(0, b0);
#pragma unroll
            for (int j = 0; j < 8; j++) {
                uint2* b = (j & 1) ? b1 : b0;
                if (j < 7) loadB(j + 1, (j & 1) ? b0 : b1);
                MMA_BF16(acc[0][j], ah[0][0], ah[0][1], ah[0][2], ah[0][3], b[0].x, b[1].x);
                MMA_BF16(acc[1][j], ah[1][0], ah[1][1], ah[1][2], ah[1][3], b[0].x, b[1].x);
                MMA_BF16(acc[0][j], ah[0][0], ah[0][1], ah[0][2], ah[0][3], b[0].y, b[1].y);
                MMA_BF16(acc[1][j], ah[1][0], ah[1][1], ah[1][2], ah[1][3], b[0].y, b[1].y);
                MMA_BF16(acc[0][j], al[0][0], al[0][1], al[0][2], al[0][3], b[0].x, b[1].x);
                MMA_BF16(acc[1][j], al[1][0], al[1][1], al[1][2], al[1][3], b[0].x, b[1].x);
            }
        }
        __syncthreads();
    }

    // epilogue
    const int N2 = N >> 1;
#pragma unroll
    for (int i = 0; i < 2; i++) {
        const int row = bm + wy * 32 + i * 16 + (lane >> 2);
#pragma unroll
        for (int j = 0; j < 8; j++) {
            const int col = bn + wx * 64 + j * 8 + (lane & 3) * 2;
            float v0 = acc[i][j][0], v1 = acc[i][j][1];
            float v2 = acc[i][j][2], v3 = acc[i][j][3];
            if (EPI == 2) {
                C2[(long)row * N2 + (col >> 1)] = bf16split2(v0, v1);
                C2[(long)(row + 8) * N2 + (col >> 1)] = bf16split2(v2, v3);
            } else {
                float* C = Cg + (long)bz * sC;
                if (EPI == 1) {
                    float m0 = maskg[(long)bz * N + col];
                    float m1 = maskg[(long)bz * N + col + 1];
                    v0 *= m0; v1 *= m1; v2 *= m0; v3 *= m1;
                }
                float2 p01; p01.x = v0; p01.y = v1;
                float2 p23; p23.x = v2; p23.y = v3;
                *reinterpret_cast<float2*>(&C[(long)row * N + col]) = p01;
                *reinterpret_cast<float2*>(&C[(long)(row + 8) * N + col]) = p23;
            }
        }
    }
}

// ---------------- split kernels ----------------
__global__ __launch_bounds__(256)
void split_pack_k(const float2* __restrict__ in, uint2* __restrict__ hl, long n2)
{
    long i = (long)blockIdx.x * blockDim.x + threadIdx.x;
    if (i < n2) {
        float2 v = in[i];
        hl[i] = bf16split2(v.x, v.y);
    }
}

// W[d][e] -> packed transpose Wt[e][d2] (pairs over d)
__global__ __launch_bounds__(256)
void transpose_split_pack_k(const float* __restrict__ W, uint2* __restrict__ t_out)
{
    __shared__ float t[32][33];
    const int d0 = blockIdx.y * 32, e0 = blockIdx.x * 32;
    const int x = threadIdx.x & 31, y = threadIdx.x >> 5;
#pragma unroll
    for (int i = 0; i < 4; i++)
        t[y + 8 * i][x] = W[(long)(d0 + y + 8 * i) * ENC_ + e0 + x];
    __syncthreads();
#pragma unroll
    for (int it = 0; it < 2; it++) {
        int idx = threadIdx.x + 256 * it;
        int e = idx >> 4, d2 = idx & 15;
        t_out[(long)(e0 + e) * (TRGD_ / 2) + (d0 >> 1) + d2] =
            bf16split2(t[2 * d2][e], t[2 * d2 + 1][e]);
    }
}

// enc_val row pairs: Ev[s][d] -> packed [s2][d] (pairs over s)
__global__ __launch_bounds__(256)
void pack_rows2_k(const float* __restrict__ in, uint2* __restrict__ hl)
{
    const int r = blockIdx.y;
    const int c = blockIdx.x * 256 + threadIdx.x;
    float v0 = in[(long)(2 * r) * TRGD_ + c];
    float v1 = in[(long)(2 * r + 1) * TRGD_ + c];
    hl[(long)r * TRGD_ + c] = bf16split2(v0, v1);
}

// ---------------- masked softmax; exact fp32 + packed uint2 outputs ---------
__global__ __launch_bounds__(256)
void masked_softmax_k(const float* __restrict__ energ, const float* __restrict__ mask,
                      float* __restrict__ wout, uint2* __restrict__ whl)
{
    const int row = blockIdx.x;
    const int b = row >> 9;
    const float4* xr = reinterpret_cast<const float4*>(energ + (long)row * SRC_);
    const float4* mr = reinterpret_cast<const float4*>(mask + (long)b * SRC_);
    float4* wr = reinterpret_cast<float4*>(wout + (long)row * SRC_);
    const int t = threadIdx.x;

    float4 xv = xr[t];
    float4 mv = mr[t];
    xv.x *= mv.x; xv.y *= mv.y; xv.z *= mv.z; xv.w *= mv.w;

    float lmax = fmaxf(fmaxf(xv.x, xv.y), fmaxf(xv.z, xv.w));
#pragma unroll
    for (int o = 16; o; o >>= 1)
        lmax = fmaxf(lmax, __shfl_xor_sync(0xffffffffu, lmax, o));

    __shared__ float redm[8];
    __shared__ float reds[8];
    if ((t & 31) == 0) redm[t >> 5] = lmax;
    __syncthreads();
    float bmax = fmaxf(fmaxf(fmaxf(redm[0], redm[1]), fmaxf(redm[2], redm[3])),
                       fmaxf(fmaxf(redm[4], redm[5]), fmaxf(redm[6], redm[7])));

    float4 ev;
    ev.x = expf(xv.x - bmax) * mv.x;
    ev.y = expf(xv.y - bmax) * mv.y;
    ev.z = expf(xv.z - bmax) * mv.z;
    ev.w = expf(xv.w - bmax) * mv.w;

    float lsum = ev.x + ev.y + ev.z + ev.w;
#pragma unroll
    for (int o = 16; o; o >>= 1)
        lsum += __shfl_xor_sync(0xffffffffu, lsum, o);
    if ((t & 31) == 0) reds[t >> 5] = lsum;
    __syncthreads();
    float bsum = reds[0] + reds[1] + reds[2] + reds[3] +
                 reds[4] + reds[5] + reds[6] + reds[7];

    float inv = 1.0f / (bsum + 1e-6f);
    ev.x *= inv; ev.y *= inv; ev.z *= inv; ev.w *= inv;
    wr[t] = ev;

    const long p = (long)row * (SRC_ / 2) + 2 * t;
    whl[p]     = bf16split2(ev.x, ev.y);
    whl[p + 1] = bf16split2(ev.z, ev.w);
}

// ---------------- launch ----------------
extern "C" void kernel_launch(void* const* d_in, const int* in_sizes, int n_in,
                              void* d_out, int out_size)
{
    const float* hidden  = (const float*)d_in[0];   // (B, TRG, TRGD)
    const float* enc_out = (const float*)d_in[1];   // (B, SRC, ENC)
    const float* enc_val = (const float*)d_in[2];   // (B, SRC, TRGD)
    const float* mask    = (const float*)d_in[3];   // (B, SRC)
    const float* W       = (const float*)d_in[4];   // (TRGD, ENC)

    float* out      = (float*)d_out;
    float* context  = out;                           // (B, TRG, TRGD)
    float* weights  = out + (long)B_ * TRG_ * SRC_;  // (B, TRG, SRC)
    float* energies = out + 2L * B_ * TRG_ * SRC_;   // (B, TRG, SRC)

    uint2 *Hd, *Eo, *Wt, *Hp, *Wg, *Ev;
    cudaGetSymbolAddress((void**)&Hd, g_Hd);
    cudaGetSymbolAddress((void**)&Eo, g_Eo);
    cudaGetSymbolAddress((void**)&Wt, g_Wt);
    cudaGetSymbolAddress((void**)&Hp, g_Hp);
    cudaGetSymbolAddress((void**)&Wg, g_Wg);
    cudaGetSymbolAddress((void**)&Ev, g_Ev);

    const size_t dyn = 2UL * 5120 * 8;   // 81,920 B
    cudaFuncSetAttribute(gemm_bf16x3<2, false>,
                         cudaFuncAttributeMaxDynamicSharedMemorySize, dyn);
    cudaFuncSetAttribute(gemm_bf16x3<1, false>,
                         cudaFuncAttributeMaxDynamicSharedMemorySize, dyn);
    cudaFuncSetAttribute(gemm_bf16x3<0, true>,
                         cudaFuncAttributeMaxDynamicSharedMemorySize, dyn);

    // splits
    {
        long n2 = (long)B_ * TRG_ * TRGD_ / 2;
        split_pack_k<<<(unsigned)((n2 + 255) / 256), 256>>>(
            (const float2*)hidden, Hd, n2);
    }
    {
        long n2 = (long)B_ * SRC_ * ENC_ / 2;
        split_pack_k<<<(unsigned)((n2 + 255) / 256), 256>>>(
            (const float2*)enc_out, Eo, n2);
    }
    transpose_split_pack_k<<<dim3(ENC_ / 32, TRGD_ / 32), 256>>>(W, Wt);
    pack_rows2_k<<<dim3(TRGD_ / 256, B_ * SRC_ / 2), 256>>>(enc_val, Ev);

    // 1) Hp = hidden @ W  -> packed uint2   (A=hidden, B=Wt, K-major)
    {
        dim3 grid(ENC_ / 128, (B_ * TRG_) / 128, 1);
        gemm_bf16x3<2, false><<<grid, 256, dyn>>>(
            Hd, Wt, nullptr, Hp, nullptr, B_ * TRG_, ENC_, TRGD_, 0, 0, 0);
    }
    // 2) energies[b] = (Hp[b] @ enc_out[b]^T) * mask[b]
    {
        dim3 grid(SRC_ / 128, TRG_ / 128, B_);
        gemm_bf16x3<1, false><<<grid, 256, dyn>>>(
            Hp, Eo, energies, nullptr, mask, TRG_, SRC_, ENC_,
            (long)TRG_ * ENC_ / 2, (long)SRC_ * ENC_ / 2, (long)TRG_ * SRC_);
    }
    // 3) masked softmax -> weights (fp32) + packed uint2
    masked_softmax_k<<<B_ * TRG_, 256>>>(energies, mask, weights, Wg);

    // 4) context[b] = weights[b] @ enc_val[b]   (B NN pairs layout)
    {
        dim3 grid(TRGD_ / 128, TRG_ / 128, B_);
        gemm_bf16x3<0, true><<<grid, 256, dyn>>>(
            Wg, Ev, context, nullptr, nullptr, TRG_, TRGD_, SRC_,
            (long)TRG_ * SRC_ / 2, (long)SRC_ / 2 * TRGD_, (long)TRG_ * TRGD_);
    }
}